// round 3
// baseline (speedup 1.0000x reference)
#include <cuda_runtime.h>

#define BATCH 32
#define LEN   1024
#define CH    512
#define NLEV  4
#define OUTN  11

// ---- scratch (no allocations allowed; __device__ globals are the sanctioned path) ----
__device__ float g_buf0[BATCH * CH * LEN];                 // 64 MB: h (persistent across levels)
__device__ float g_buf1[BATCH * CH * LEN];                 // 64 MB: intermediate h1
__device__ float g_wp[NLEV * 2 * 2 * CH * CH];             // 16 MB: packed weights [lev][conv][k=2C][m=C]

// ============================================================================
// Repack weights: A_p[k][m] for k in [0,2C):
//   k <  C : tap 1 (current sample),  ci = k
//   k >= C : tap 0 (shifted by d),    ci = k - C
// Source layout: w[lev][co][ci][tap], tap innermost (K=2).
// ============================================================================
__global__ void repack_kernel(const float* __restrict__ w1, const float* __restrict__ w2) {
    int idx = blockIdx.x * blockDim.x + threadIdx.x;
    const int total = NLEV * 2 * 2 * CH * CH;
    if (idx >= total) return;
    int m   = idx % CH;
    int k   = (idx / CH) % (2 * CH);
    int j   = (idx / (CH * 2 * CH)) % 2;      // 0 = conv1 (w1), 1 = conv2 (w2)
    int lev = idx / (CH * 2 * CH * 2);
    const float* w = (j == 0) ? w1 : w2;
    int tap = (k < CH) ? 1 : 0;
    int ci  = (k < CH) ? k : k - CH;
    g_wp[idx] = w[((lev * CH + m) * CH + ci) * 2 + tap];
}

// ============================================================================
// Embedding gather: h[b][c][l] = emb[x[b][l]][c]
// ============================================================================
__global__ void embed_kernel(const int* __restrict__ x, const float* __restrict__ emb) {
    int idx = blockIdx.x * blockDim.x + threadIdx.x;   // B*C*L threads
    int l = idx % LEN;
    int c = (idx / LEN) % CH;
    int b = idx / (LEN * CH);
    int tok = x[b * LEN + l];
    g_buf0[idx] = emb[tok * CH + c];
}

// ============================================================================
// Causal dilated conv as GEMM.  128x128 tile, BK=8, 8x8 per-thread fragment.
//   out[b,m,n] = bias[m] + sum_{k<2C} Ap[k][m] * Bmat[k][n]
//   Bmat[k][n] = k<C ? h[b][k][n] : h[b][k-C][n-d]  (0 if n-d < 0)
// dir==0: in = buf0, out = buf1, no residual      (conv1)
// dir==1: in = buf1, out = buf0, residual = buf0  (conv2 + res + relu)
// ============================================================================
__global__ __launch_bounds__(256) void conv_gemm_kernel(int wbase, const float* __restrict__ bias,
                                                        int d, int dir) {
    __shared__ float As[8][128];
    __shared__ float Bs[8][128];

    const float* __restrict__ hin  = dir ? g_buf1 : g_buf0;
    float*       __restrict__ hout = dir ? g_buf0 : g_buf1;
    const float* __restrict__ res  = g_buf0;   // only used when dir==1
    const float* __restrict__ Ap   = g_wp + wbase;

    const int tid = threadIdx.x;
    const int tx  = tid & 15;        // 0..15  -> n
    const int ty  = tid >> 4;        // 0..15  -> m
    const int b   = blockIdx.z;
    const int m0  = blockIdx.y * 128;
    const int l0  = blockIdx.x * 128;

    const float* hb = hin + b * CH * LEN;

    // load indices (each thread: 4 floats of A, 4 floats of B per k-tile)
    const int ak = tid >> 5;             // 0..7
    const int am = (tid & 31) * 4;       // 0..124
    const int bk = tid >> 5;
    const int bn = (tid & 31) * 4;

    float acc[8][8];
#pragma unroll
    for (int i = 0; i < 8; i++)
#pragma unroll
        for (int j = 0; j < 8; j++) acc[i][j] = 0.f;

    for (int kk = 0; kk < 2 * CH; kk += 8) {
        // --- A tile: coalesced float4 from packed weights ---
        float4 av = *reinterpret_cast<const float4*>(&Ap[(kk + ak) * CH + m0 + am]);
        *reinterpret_cast<float4*>(&As[ak][am]) = av;

        // --- B tile: activation rows, uniform shift within the tile ---
        const int  inFirstHalf = (kk < CH);
        const int  ci    = inFirstHalf ? (kk + bk) : (kk - CH + bk);
        const int  shift = inFirstHalf ? 0 : d;
        const float* hr  = hb + ci * LEN;
        const int  lb    = l0 + bn - shift;
        Bs[bk][bn + 0] = (lb + 0 >= 0) ? hr[lb + 0] : 0.f;
        Bs[bk][bn + 1] = (lb + 1 >= 0) ? hr[lb + 1] : 0.f;
        Bs[bk][bn + 2] = (lb + 2 >= 0) ? hr[lb + 2] : 0.f;
        Bs[bk][bn + 3] = (lb + 3 >= 0) ? hr[lb + 3] : 0.f;

        __syncthreads();

#pragma unroll
        for (int k = 0; k < 8; k++) {
            float a[8], bb[8];
            float4 a0 = *reinterpret_cast<const float4*>(&As[k][ty * 8]);
            float4 a1 = *reinterpret_cast<const float4*>(&As[k][ty * 8 + 4]);
            float4 b0 = *reinterpret_cast<const float4*>(&Bs[k][tx * 8]);
            float4 b1 = *reinterpret_cast<const float4*>(&Bs[k][tx * 8 + 4]);
            a[0]=a0.x; a[1]=a0.y; a[2]=a0.z; a[3]=a0.w; a[4]=a1.x; a[5]=a1.y; a[6]=a1.z; a[7]=a1.w;
            bb[0]=b0.x; bb[1]=b0.y; bb[2]=b0.z; bb[3]=b0.w; bb[4]=b1.x; bb[5]=b1.y; bb[6]=b1.z; bb[7]=b1.w;
#pragma unroll
            for (int i = 0; i < 8; i++)
#pragma unroll
                for (int j = 0; j < 8; j++)
                    acc[i][j] = fmaf(a[i], bb[j], acc[i][j]);
        }
        __syncthreads();
    }

    // epilogue: bias + relu (+ residual + relu)
#pragma unroll
    for (int i = 0; i < 8; i++) {
        const int m = m0 + ty * 8 + i;
        const float bv = bias[m];
        const int rowoff = (b * CH + m) * LEN;
#pragma unroll
        for (int j = 0; j < 8; j++) {
            const int n = l0 + tx * 8 + j;
            float v = fmaxf(acc[i][j] + bv, 0.f);
            if (dir) v = fmaxf(v + res[rowoff + n], 0.f);
            hout[rowoff + n] = v;
        }
    }
}

// ============================================================================
// Decoder: y[b,l,o] = mask[b,l] ? (sum_c h[b,c,l]*dec_w[o,c] + dec_b[o]) : 0
// mask arrives as int32 (harness materializes bools as int32).
// ============================================================================
__global__ __launch_bounds__(128) void decode_kernel(const int* __restrict__ mask,
                                                     const float* __restrict__ dec_w,
                                                     const float* __restrict__ dec_b,
                                                     float* __restrict__ y) {
    __shared__ float sw[OUTN * CH];
    const int tid = threadIdx.x;
    for (int i = tid; i < OUTN * CH; i += 128) sw[i] = dec_w[i];
    __syncthreads();

    const int b = blockIdx.y;
    const int l = blockIdx.x * 128 + tid;
    const float* hb = g_buf0 + b * CH * LEN + l;

    float acc[OUTN];
#pragma unroll
    for (int o = 0; o < OUTN; o++) acc[o] = 0.f;

    for (int c = 0; c < CH; c++) {
        const float hv = hb[c * LEN];
#pragma unroll
        for (int o = 0; o < OUTN; o++) acc[o] = fmaf(hv, sw[o * CH + c], acc[o]);
    }

    const int mk = mask[b * LEN + l];
    float* yo = y + (b * LEN + l) * OUTN;
#pragma unroll
    for (int o = 0; o < OUTN; o++) yo[o] = mk ? (acc[o] + dec_b[o]) : 0.f;
}

// ============================================================================
// launch
// ============================================================================
extern "C" void kernel_launch(void* const* d_in, const int* in_sizes, int n_in,
                              void* d_out, int out_size) {
    const int*   x     = (const int*)d_in[0];
    const int*   mask  = (const int*)d_in[1];
    const float* emb   = (const float*)d_in[2];
    const float* w1    = (const float*)d_in[3];
    const float* b1    = (const float*)d_in[4];
    const float* w2    = (const float*)d_in[5];
    const float* b2    = (const float*)d_in[6];
    const float* dec_w = (const float*)d_in[7];
    const float* dec_b = (const float*)d_in[8];
    float*       y     = (float*)d_out;

    // 1) repack weights into k-major [2C x C] per conv
    {
        const int total = NLEV * 2 * 2 * CH * CH;
        repack_kernel<<<(total + 255) / 256, 256>>>(w1, w2);
    }

    // 2) embedding gather -> buf0
    {
        const int total = BATCH * CH * LEN;
        embed_kernel<<<total / 256, 256>>>(x, emb);
    }

    // 3) TCN levels
    dim3 grid(LEN / 128, CH / 128, BATCH);
    for (int lev = 0; lev < NLEV; lev++) {
        const int d = 1 << lev;
        const int wbase1 = (lev * 2 + 0) * 2 * CH * CH;
        const int wbase2 = (lev * 2 + 1) * 2 * CH * CH;
        conv_gemm_kernel<<<grid, 256>>>(wbase1, b1 + lev * CH, d, 0);  // buf0 -> buf1
        conv_gemm_kernel<<<grid, 256>>>(wbase2, b2 + lev * CH, d, 1);  // buf1 (+res buf0) -> buf0
    }

    // 4) decode + mask
    decode_kernel<<<dim3(LEN / 128, BATCH), 128>>>(mask, dec_w, dec_b, y);
}

// round 6
// speedup vs baseline: 3.5721x; 3.5721x over previous
#include <cuda_runtime.h>
#include <cuda_bf16.h>
#include <cstdint>

#define BATCH 32
#define LEN   1024
#define CH    512
#define NLEV  4
#define OUTN  11
#define KTOT  1024          // 2*CH (two taps concatenated along k)
#define BK    64
#define NCHUNK (KTOT/BK)    // 16
#define TM    128
#define TN    128

// ---- global scratch (device globals; no allocations allowed) ----
__device__ __nv_bfloat16 g_a_hi[BATCH*LEN*CH];   // act buffer A (hi)
__device__ __nv_bfloat16 g_a_lo[BATCH*LEN*CH];   // act buffer A (lo)
__device__ __nv_bfloat16 g_b_hi[BATCH*LEN*CH];   // act buffer B (hi)
__device__ __nv_bfloat16 g_b_lo[BATCH*LEN*CH];   // act buffer B (lo)
__device__ __nv_bfloat16 g_w_hi[NLEV*2*CH*KTOT]; // packed weights hi [lev][conv][co][k]
__device__ __nv_bfloat16 g_w_lo[NLEV*2*CH*KTOT]; // packed weights lo

// ============================================================================
// helpers
// ============================================================================
__device__ __forceinline__ uint32_t smem_u32(const void* p) {
    uint32_t a;
    asm("{ .reg .u64 t; cvta.to.shared.u64 t, %1; cvt.u32.u64 %0, t; }" : "=r"(a) : "l"(p));
    return a;
}

__device__ __forceinline__ void cpa16(uint32_t dst, const void* src, uint32_t sz) {
    asm volatile("cp.async.cg.shared.global [%0], [%1], 16, %2;"
                 :: "r"(dst), "l"(src), "r"(sz) : "memory");
}

__device__ __forceinline__ void ldsm4(uint32_t* r, uint32_t a) {
    asm volatile("ldmatrix.sync.aligned.m8n8.x4.shared.b16 {%0,%1,%2,%3}, [%4];"
                 : "=r"(r[0]), "=r"(r[1]), "=r"(r[2]), "=r"(r[3]) : "r"(a));
}

__device__ __forceinline__ void mma16816(float* d, const uint32_t* a, const uint32_t* b) {
    asm volatile("mma.sync.aligned.m16n8k16.row.col.f32.bf16.bf16.f32 "
                 "{%0,%1,%2,%3}, {%4,%5,%6,%7}, {%8,%9}, {%0,%1,%2,%3};"
                 : "+f"(d[0]), "+f"(d[1]), "+f"(d[2]), "+f"(d[3])
                 : "r"(a[0]), "r"(a[1]), "r"(a[2]), "r"(a[3]), "r"(b[0]), "r"(b[1]));
}

__device__ __forceinline__ void split_bf16(float v, __nv_bfloat16& h, __nv_bfloat16& l) {
    h = __float2bfloat16(v);
    l = __float2bfloat16(v - __bfloat162float(h));
}

// ============================================================================
// repack weights -> [lev][conv][co][k] k-major bf16 hi/lo; k<CH: tap1, k>=CH: tap0
// ============================================================================
__global__ void repack_kernel(const float* __restrict__ w1, const float* __restrict__ w2) {
    int idx = blockIdx.x * blockDim.x + threadIdx.x;
    const int total = NLEV * 2 * CH * KTOT;
    if (idx >= total) return;
    int k    = idx % KTOT;
    int co   = (idx / KTOT) % CH;
    int conv = (idx / (KTOT * CH)) % 2;
    int lev  = idx / (KTOT * CH * 2);
    const float* w = conv ? w2 : w1;
    int tap = (k < CH) ? 1 : 0;
    int ci  = k & (CH - 1);
    float v = w[((lev * CH + co) * CH + ci) * 2 + tap];
    __nv_bfloat16 h, l;
    split_bf16(v, h, l);
    g_w_hi[idx] = h;
    g_w_lo[idx] = l;
}

// ============================================================================
// embedding gather -> act buffer A, [b][l][c] layout, bf16 hi/lo split
// ============================================================================
__global__ void embed_kernel(const int* __restrict__ x, const float* __restrict__ emb) {
    int idx = blockIdx.x * blockDim.x + threadIdx.x;   // (b*LEN+l)*CH + c
    int c = idx % CH;
    int bl = idx / CH;
    int tok = x[bl];
    float v = emb[tok * CH + c];
    __nv_bfloat16 h, l;
    split_bf16(v, h, l);
    g_a_hi[idx] = h;
    g_a_lo[idx] = l;
}

// ============================================================================
// conv as HMMA GEMM: D[l, co] = sum_k A[l,k] * W[co,k]
//   A rows: act[b][l][:] for k<CH (tap1) / act[b][l-d][:] for k>=CH (tap0)
//   split-bf16: acc += Ah*Wh + Ah*Wl + Al*Wh   (fp32 accumulate)
// dir==0: in=A, out=B                 (conv1)
// dir==1: in=B, out=A, residual=A    (conv2 + res + relu)
// ============================================================================
#define SST     65536           // 64KB per stage
#define OFF_AH  0
#define OFF_AL  16384
#define OFF_WH  32768
#define OFF_WL  49152
#define SMEM_SZ (1024 + 2*SST)  // bias(512)+pad, two stages

__global__ __launch_bounds__(256) void conv_hmma_kernel(int wbase, const float* __restrict__ bias,
                                                        int d, int dir) {
    extern __shared__ char sm[];
    const uint32_t sb    = smem_u32(sm);
    const uint32_t tiles = sb + 1024;

    const __nv_bfloat16* __restrict__ act_hi = dir ? g_b_hi : g_a_hi;
    const __nv_bfloat16* __restrict__ act_lo = dir ? g_b_lo : g_a_lo;
    __nv_bfloat16* __restrict__ out_hi = dir ? g_a_hi : g_b_hi;
    __nv_bfloat16* __restrict__ out_lo = dir ? g_a_lo : g_b_lo;

    const int tid    = threadIdx.x;
    const int lane   = tid & 31;
    const int wid    = tid >> 5;
    const int warp_m = wid & 3;
    const int warp_n = wid >> 2;
    const int l0     = blockIdx.x * TM;
    const int co0    = blockIdx.y * TN;
    const int b      = blockIdx.z;

    if (tid < 128) ((float*)sm)[tid] = bias[co0 + tid];

    // per-thread load coords (same for all 4 tiles)
    int lr[4], lseg[4];
    uint32_t lsw[4];
#pragma unroll
    for (int i = 0; i < 4; i++) {
        int u = tid + 256 * i;
        lr[i]   = u >> 3;
        lseg[i] = u & 7;
        lsw[i]  = (uint32_t)(lr[i] * 128 + ((lseg[i] ^ (lr[i] & 7)) << 4));
    }

    // ---- chunk loader (cp.async) ----
    auto load_chunk = [&](int c) {
        const uint32_t st   = tiles + (c & 1) * SST;
        const int shift     = (c >= 8) ? d : 0;
        const int cb        = (c & 7) * BK;
        const int wk        = wbase + c * BK;
#pragma unroll
        for (int i = 0; i < 4; i++) {
            const int r = lr[i], seg = lseg[i];
            const uint32_t sw = lsw[i];
            int ls = l0 + r - shift;
            uint32_t pr = (ls >= 0) ? 16u : 0u;
            if (ls < 0) ls = 0;
            const int aoff = (b * LEN + ls) * CH + cb + seg * 8;
            cpa16(st + OFF_AH + sw, act_hi + aoff, pr);
            cpa16(st + OFF_AL + sw, act_lo + aoff, pr);
            const int woff = wk + (co0 + r) * KTOT + seg * 8;
            cpa16(st + OFF_WH + sw, g_w_hi + woff, 16u);
            cpa16(st + OFF_WL + sw, g_w_lo + woff, 16u);
        }
        asm volatile("cp.async.commit_group;" ::: "memory");
    };

    float acc[2][8][4];
#pragma unroll
    for (int mt = 0; mt < 2; mt++)
#pragma unroll
        for (int nt = 0; nt < 8; nt++)
#pragma unroll
            for (int q = 0; q < 4; q++) acc[mt][nt][q] = 0.f;

    load_chunk(0);

    // fragment address components
    const int arow   = lane & 15;
    const int ak16   = (lane >> 4);                 // 0/1 -> +16B
    const int brow   = (lane & 7) + ((lane >> 4) << 3);
    const int bk16   = (lane >> 3) & 1;             // 0/1 -> +16B

    for (int c = 0; c < NCHUNK; c++) {
        if (c < NCHUNK - 1) load_chunk(c + 1);
        if (c < NCHUNK - 1) asm volatile("cp.async.wait_group 1;" ::: "memory");
        else                asm volatile("cp.async.wait_group 0;" ::: "memory");
        __syncthreads();

        const uint32_t st = tiles + (c & 1) * SST;
        const uint32_t AH = st + OFF_AH, AL = st + OFF_AL;
        const uint32_t WH = st + OFF_WH, WL = st + OFF_WL;

#pragma unroll
        for (int ks = 0; ks < 4; ks++) {
            uint32_t ah[2][4], al[2][4], wh[4][4], wl[4][4];
            const int akb = ks * 32 + ak16 * 16;
#pragma unroll
            for (int mt = 0; mt < 2; mt++) {
                const int rr = warp_m * 32 + mt * 16 + arow;
                const uint32_t off = (uint32_t)(rr * 128 + ((((akb >> 4)) ^ (rr & 7)) << 4));
                ldsm4(ah[mt], AH + off);
                ldsm4(al[mt], AL + off);
            }
            const int bkb = ks * 32 + bk16 * 16;
#pragma unroll
            for (int j = 0; j < 4; j++) {
                const int rr = warp_n * 64 + j * 16 + brow;
                const uint32_t off = (uint32_t)(rr * 128 + ((((bkb >> 4)) ^ (rr & 7)) << 4));
                ldsm4(wh[j], WH + off);
                ldsm4(wl[j], WL + off);
            }
#pragma unroll
            for (int mt = 0; mt < 2; mt++)
#pragma unroll
                for (int nt = 0; nt < 8; nt++) {
                    const uint32_t* bh = &wh[nt >> 1][(nt & 1) * 2];
                    const uint32_t* bl = &wl[nt >> 1][(nt & 1) * 2];
                    mma16816(acc[mt][nt], ah[mt], bh);
                    mma16816(acc[mt][nt], ah[mt], bl);
                    mma16816(acc[mt][nt], al[mt], bh);
                }
        }
        __syncthreads();
    }

    // ---- epilogue: bias + relu (+ residual + relu), split to hi/lo bf16 ----
    const float* bs = (const float*)sm;
#pragma unroll
    for (int mt = 0; mt < 2; mt++) {
        const int rbase = warp_m * 32 + mt * 16 + (lane >> 2);
#pragma unroll
        for (int half = 0; half < 2; half++) {
            const int row = rbase + half * 8;
            const int l   = l0 + row;
            const int rowoff = (b * LEN + l) * CH + co0;
#pragma unroll
            for (int nt = 0; nt < 8; nt++) {
                const int c0 = warp_n * 64 + nt * 8 + (lane & 3) * 2;
                float v0 = fmaxf(acc[mt][nt][half * 2 + 0] + bs[c0],     0.f);
                float v1 = fmaxf(acc[mt][nt][half * 2 + 1] + bs[c0 + 1], 0.f);
                const int off = rowoff + c0;
                if (dir) {
                    uint32_t rh = *(const uint32_t*)(g_a_hi + off);
                    uint32_t rl = *(const uint32_t*)(g_a_lo + off);
                    const __nv_bfloat162 h2 = *(__nv_bfloat162*)&rh;
                    const __nv_bfloat162 l2 = *(__nv_bfloat162*)&rl;
                    v0 = fmaxf(v0 + __bfloat162float(h2.x) + __bfloat162float(l2.x), 0.f);
                    v1 = fmaxf(v1 + __bfloat162float(h2.y) + __bfloat162float(l2.y), 0.f);
                }
                __nv_bfloat16 h0, lo0, h1, lo1;
                split_bf16(v0, h0, lo0);
                split_bf16(v1, h1, lo1);
                __nv_bfloat162 hh(h0, h1), ll(lo0, lo1);
                *(uint32_t*)(out_hi + off) = *(uint32_t*)&hh;
                *(uint32_t*)(out_lo + off) = *(uint32_t*)&ll;
            }
        }
    }
}

// ============================================================================
// decoder: y[b,l,o] = mask ? sum_c (hi+lo)(b,l,c) * dec_w[o,c] + dec_b[o] : 0
// ============================================================================
__global__ __launch_bounds__(128) void decode_kernel(const int* __restrict__ mask,
                                                     const float* __restrict__ dec_w,
                                                     const float* __restrict__ dec_b,
                                                     float* __restrict__ y) {
    __shared__ float sw[OUTN * CH];
    const int tid = threadIdx.x;
    for (int i = tid; i < OUTN * CH; i += 128) sw[i] = dec_w[i];
    __syncthreads();

    const int b = blockIdx.y;
    const int l = blockIdx.x * 128 + tid;
    const int base = (b * LEN + l) * CH;

    float acc[OUTN];
#pragma unroll
    for (int o = 0; o < OUTN; o++) acc[o] = 0.f;

    for (int c = 0; c < CH; c += 8) {
        uint4 H = *(const uint4*)(g_a_hi + base + c);
        uint4 L = *(const uint4*)(g_a_lo + base + c);
        const __nv_bfloat16* hp = (const __nv_bfloat16*)&H;
        const __nv_bfloat16* lp = (const __nv_bfloat16*)&L;
#pragma unroll
        for (int q = 0; q < 8; q++) {
            float hv = __bfloat162float(hp[q]) + __bfloat162float(lp[q]);
#pragma unroll
            for (int o = 0; o < OUTN; o++) acc[o] = fmaf(hv, sw[o * CH + c + q], acc[o]);
        }
    }

    const int mk = mask[b * LEN + l];
    float* yo = y + (b * LEN + l) * OUTN;
#pragma unroll
    for (int o = 0; o < OUTN; o++) yo[o] = mk ? (acc[o] + dec_b[o]) : 0.f;
}

// ============================================================================
// launch
// ============================================================================
extern "C" void kernel_launch(void* const* d_in, const int* in_sizes, int n_in,
                              void* d_out, int out_size) {
    const int*   x     = (const int*)d_in[0];
    const int*   mask  = (const int*)d_in[1];
    const float* emb   = (const float*)d_in[2];
    const float* w1    = (const float*)d_in[3];
    const float* b1    = (const float*)d_in[4];
    const float* w2    = (const float*)d_in[5];
    const float* b2    = (const float*)d_in[6];
    const float* dec_w = (const float*)d_in[7];
    const float* dec_b = (const float*)d_in[8];
    float*       y     = (float*)d_out;

    cudaFuncSetAttribute(conv_hmma_kernel, cudaFuncAttributeMaxDynamicSharedMemorySize, SMEM_SZ);

    // 1) repack weights (split bf16, k-major)
    {
        const int total = NLEV * 2 * CH * KTOT;
        repack_kernel<<<(total + 255) / 256, 256>>>(w1, w2);
    }
    // 2) embedding gather -> act buffer A
    {
        const int total = BATCH * LEN * CH;
        embed_kernel<<<total / 256, 256>>>(x, emb);
    }
    // 3) TCN levels on tensor cores (HMMA)
    dim3 grid(LEN / TM, CH / TN, BATCH);
    for (int lev = 0; lev < NLEV; lev++) {
        const int d = 1 << lev;
        const int wb1 = (lev * 2 + 0) * CH * KTOT;
        const int wb2 = (lev * 2 + 1) * CH * KTOT;
        conv_hmma_kernel<<<grid, 256, SMEM_SZ>>>(wb1, b1 + lev * CH, d, 0);  // A -> B
        conv_hmma_kernel<<<grid, 256, SMEM_SZ>>>(wb2, b2 + lev * CH, d, 1);  // B (+res A) -> A
    }
    // 4) decode + mask
    decode_kernel<<<dim3(LEN / 128, BATCH), 128>>>(mask, dec_w, dec_b, y);
}

// round 8
// speedup vs baseline: 3.8971x; 1.0910x over previous
#include <cuda_runtime.h>
#include <cuda_bf16.h>
#include <cstdint>

#define BATCH 32
#define LEN   1024
#define CH    512
#define NLEV  4
#define OUTN  11
#define KTOT  1024          // 2*CH (two taps concatenated along k)
#define BK    32
#define NCHUNK (KTOT/BK)    // 32
#define TM    128
#define TN    128

// ---- global scratch (device globals; no allocations allowed) ----
__device__ __nv_bfloat16 g_a_hi[BATCH*LEN*CH];   // act buffer A (hi)
__device__ __nv_bfloat16 g_a_lo[BATCH*LEN*CH];   // act buffer A (lo)
__device__ __nv_bfloat16 g_b_hi[BATCH*LEN*CH];   // act buffer B (hi)
__device__ __nv_bfloat16 g_b_lo[BATCH*LEN*CH];   // act buffer B (lo)
__device__ __nv_bfloat16 g_w_hi[NLEV*2*CH*KTOT]; // packed weights hi [lev][conv][co][k]
__device__ __nv_bfloat16 g_w_lo[NLEV*2*CH*KTOT]; // packed weights lo

// ============================================================================
// helpers
// ============================================================================
__device__ __forceinline__ uint32_t smem_u32(const void* p) {
    uint32_t a;
    asm("{ .reg .u64 t; cvta.to.shared.u64 t, %1; cvt.u32.u64 %0, t; }" : "=r"(a) : "l"(p));
    return a;
}

__device__ __forceinline__ void cpa16(uint32_t dst, const void* src, uint32_t sz) {
    asm volatile("cp.async.cg.shared.global [%0], [%1], 16, %2;"
                 :: "r"(dst), "l"(src), "r"(sz) : "memory");
}

__device__ __forceinline__ void ldsm4(uint32_t* r, uint32_t a) {
    asm volatile("ldmatrix.sync.aligned.m8n8.x4.shared.b16 {%0,%1,%2,%3}, [%4];"
                 : "=r"(r[0]), "=r"(r[1]), "=r"(r[2]), "=r"(r[3]) : "r"(a));
}

__device__ __forceinline__ void mma16816(float* d, const uint32_t* a, const uint32_t* b) {
    asm volatile("mma.sync.aligned.m16n8k16.row.col.f32.bf16.bf16.f32 "
                 "{%0,%1,%2,%3}, {%4,%5,%6,%7}, {%8,%9}, {%0,%1,%2,%3};"
                 : "+f"(d[0]), "+f"(d[1]), "+f"(d[2]), "+f"(d[3])
                 : "r"(a[0]), "r"(a[1]), "r"(a[2]), "r"(a[3]), "r"(b[0]), "r"(b[1]));
}

__device__ __forceinline__ void split_bf16(float v, __nv_bfloat16& h, __nv_bfloat16& l) {
    h = __float2bfloat16(v);
    l = __float2bfloat16(v - __bfloat162float(h));
}

// ============================================================================
// repack weights -> [lev][conv][co][k] k-major bf16 hi/lo; k<CH: tap1, k>=CH: tap0
// ============================================================================
__global__ void repack_kernel(const float* __restrict__ w1, const float* __restrict__ w2) {
    int idx = blockIdx.x * blockDim.x + threadIdx.x;
    const int total = NLEV * 2 * CH * KTOT;
    if (idx >= total) return;
    int k    = idx % KTOT;
    int co   = (idx / KTOT) % CH;
    int conv = (idx / (KTOT * CH)) % 2;
    int lev  = idx / (KTOT * CH * 2);
    const float* w = conv ? w2 : w1;
    int tap = (k < CH) ? 1 : 0;
    int ci  = k & (CH - 1);
    float v = w[((lev * CH + co) * CH + ci) * 2 + tap];
    __nv_bfloat16 h, l;
    split_bf16(v, h, l);
    g_w_hi[idx] = h;
    g_w_lo[idx] = l;
}

// ============================================================================
// embedding gather -> act buffer A, [b][l][c] layout, bf16 hi/lo split
// ============================================================================
__global__ void embed_kernel(const int* __restrict__ x, const float* __restrict__ emb) {
    int idx = blockIdx.x * blockDim.x + threadIdx.x;   // (b*LEN+l)*CH + c
    int c = idx % CH;
    int bl = idx / CH;
    int tok = x[bl];
    float v = emb[tok * CH + c];
    __nv_bfloat16 h, l;
    split_bf16(v, h, l);
    g_a_hi[idx] = h;
    g_a_lo[idx] = l;
}

// ============================================================================
// conv as HMMA GEMM: D[l, co] = sum_k A[l,k] * W[co,k]
//   split-bf16: acc += Ah*Wh + Ah*Wl + Al*Wh (fp32 accumulate)
// SMEM stage (32KB): A tile 128 rows x 128B (hi 64B | lo 64B), W tile same.
// 3 stages + 2 CTAs/SM for latency hiding.
// dir==0: in=A, out=B              (conv1)
// dir==1: in=B, out=A, residual=A  (conv2 + res + relu)
// ============================================================================
#define SST     32768           // 32KB per stage
#define OFF_A   0
#define OFF_W   16384
#define NSTAGE  3
#define SMEM_SZ (1024 + NSTAGE*SST)

__global__ __launch_bounds__(256, 2) void conv_hmma_kernel(int wbase, const float* __restrict__ bias,
                                                           int d, int dir) {
    extern __shared__ char sm[];
    const uint32_t sb    = smem_u32(sm);
    const uint32_t tiles = sb + 1024;

    const __nv_bfloat16* __restrict__ act_hi = dir ? g_b_hi : g_a_hi;
    const __nv_bfloat16* __restrict__ act_lo = dir ? g_b_lo : g_a_lo;
    __nv_bfloat16* __restrict__ out_hi = dir ? g_a_hi : g_b_hi;
    __nv_bfloat16* __restrict__ out_lo = dir ? g_a_lo : g_b_lo;

    const int tid    = threadIdx.x;
    const int lane   = tid & 31;
    const int wid    = tid >> 5;
    const int warp_m = wid & 3;
    const int warp_n = wid >> 2;
    const int l0     = blockIdx.x * TM;
    const int co0    = blockIdx.y * TN;
    const int b      = blockIdx.z;

    if (tid < 128) ((float*)sm)[tid] = bias[co0 + tid];

    // per-thread load coords: u in 0..1023 -> row r (0..127), seg (0..7)
    // seg<4: hi half (bytes 0-63), seg>=4: lo half (bytes 64-127)
    int lr[4], lseg[4];
    uint32_t lsw[4];
#pragma unroll
    for (int i = 0; i < 4; i++) {
        int u = tid + 256 * i;
        lr[i]   = u >> 3;
        lseg[i] = u & 7;
        lsw[i]  = (uint32_t)(lr[i] * 128 + ((lseg[i] ^ (lr[i] & 7)) << 4));
    }

    // ---- chunk loader (cp.async), BK=32 elems per chunk ----
    auto load_chunk = [&](int c) {
        const uint32_t st = tiles + (c % NSTAGE) * SST;
        const int shift   = (c >= 16) ? d : 0;
        const int cb      = (c & 15) * BK;
        const int wk      = wbase + c * BK;
#pragma unroll
        for (int i = 0; i < 4; i++) {
            const int r = lr[i], seg = lseg[i];
            int ls = l0 + r - shift;
            uint32_t pr = (ls >= 0) ? 16u : 0u;
            if (ls < 0) ls = 0;
            const __nv_bfloat16* asrc = (seg < 4) ? act_hi : act_lo;
            const int aoff = (b * LEN + ls) * CH + cb + (seg & 3) * 8;
            cpa16(st + OFF_A + lsw[i], asrc + aoff, pr);
            const __nv_bfloat16* wsrc = (seg < 4) ? g_w_hi : g_w_lo;
            const int woff = wk + (co0 + r) * KTOT + (seg & 3) * 8;
            cpa16(st + OFF_W + lsw[i], wsrc + woff, 16u);
        }
        asm volatile("cp.async.commit_group;" ::: "memory");
    };

    float acc[2][8][4];
#pragma unroll
    for (int mt = 0; mt < 2; mt++)
#pragma unroll
        for (int nt = 0; nt < 8; nt++)
#pragma unroll
            for (int q = 0; q < 4; q++) acc[mt][nt][q] = 0.f;

    load_chunk(0);
    load_chunk(1);

    // fragment address components
    const int arow = lane & 15;
    const int ak16 = (lane >> 4);                 // +16B within kstep
    const int brow = (lane & 7) + ((lane >> 4) << 3);
    const int bk16 = (lane >> 3) & 1;

    for (int c = 0; c < NCHUNK; c++) {
        if (c + 1 < NCHUNK) asm volatile("cp.async.wait_group 1;" ::: "memory");
        else                asm volatile("cp.async.wait_group 0;" ::: "memory");
        __syncthreads();

        const uint32_t st = tiles + (c % NSTAGE) * SST;
        const uint32_t AT = st + OFF_A;
        const uint32_t WT = st + OFF_W;

#pragma unroll
        for (int ks = 0; ks < 2; ks++) {
            uint32_t ah[2][4], al[2][4];
            const int hkb = ks * 32 + ak16 * 16;          // hi bytes within row
#pragma unroll
            for (int mt = 0; mt < 2; mt++) {
                const int rr = warp_m * 32 + mt * 16 + arow;
                const uint32_t oh = (uint32_t)(rr * 128 + (((hkb >> 4) ^ (rr & 7)) << 4));
                const uint32_t ol = (uint32_t)(rr * 128 + ((((hkb + 64) >> 4) ^ (rr & 7)) << 4));
                ldsm4(ah[mt], AT + oh);
                ldsm4(al[mt], AT + ol);
            }
            const int wkb = ks * 32 + bk16 * 16;
#pragma unroll
            for (int j = 0; j < 4; j++) {
                uint32_t wh[4], wl[4];
                const int rr = warp_n * 64 + j * 16 + brow;
                const uint32_t oh = (uint32_t)(rr * 128 + (((wkb >> 4) ^ (rr & 7)) << 4));
                const uint32_t ol = (uint32_t)(rr * 128 + ((((wkb + 64) >> 4) ^ (rr & 7)) << 4));
                ldsm4(wh, WT + oh);
                ldsm4(wl, WT + ol);
#pragma unroll
                for (int mt = 0; mt < 2; mt++)
#pragma unroll
                    for (int h = 0; h < 2; h++) {
                        const int nt = j * 2 + h;
                        mma16816(acc[mt][nt], ah[mt], &wh[h * 2]);
                        mma16816(acc[mt][nt], ah[mt], &wl[h * 2]);
                        mma16816(acc[mt][nt], al[mt], &wh[h * 2]);
                    }
            }
        }
        __syncthreads();
        if (c + 2 < NCHUNK) load_chunk(c + 2);
    }

    // ---- epilogue: bias + relu (+ residual + relu), split to hi/lo bf16 ----
    const float* bs = (const float*)sm;
#pragma unroll
    for (int mt = 0; mt < 2; mt++) {
        const int rbase = warp_m * 32 + mt * 16 + (lane >> 2);
#pragma unroll
        for (int half = 0; half < 2; half++) {
            const int row = rbase + half * 8;
            const int l   = l0 + row;
            const int rowoff = (b * LEN + l) * CH + co0;
#pragma unroll
            for (int nt = 0; nt < 8; nt++) {
                const int c0 = warp_n * 64 + nt * 8 + (lane & 3) * 2;
                float v0 = fmaxf(acc[mt][nt][half * 2 + 0] + bs[c0],     0.f);
                float v1 = fmaxf(acc[mt][nt][half * 2 + 1] + bs[c0 + 1], 0.f);
                const int off = rowoff + c0;
                if (dir) {
                    uint32_t rh = *(const uint32_t*)(g_a_hi + off);
                    uint32_t rl = *(const uint32_t*)(g_a_lo + off);
                    const __nv_bfloat162 h2 = *(__nv_bfloat162*)&rh;
                    const __nv_bfloat162 l2 = *(__nv_bfloat162*)&rl;
                    v0 = fmaxf(v0 + __bfloat162float(h2.x) + __bfloat162float(l2.x), 0.f);
                    v1 = fmaxf(v1 + __bfloat162float(h2.y) + __bfloat162float(l2.y), 0.f);
                }
                __nv_bfloat16 h0, lo0, h1, lo1;
                split_bf16(v0, h0, lo0);
                split_bf16(v1, h1, lo1);
                __nv_bfloat162 hh(h0, h1), ll(lo0, lo1);
                *(uint32_t*)(out_hi + off) = *(uint32_t*)&hh;
                *(uint32_t*)(out_lo + off) = *(uint32_t*)&ll;
            }
        }
    }
}

// ============================================================================
// decoder: y[b,l,o] = mask ? sum_c (hi+lo)(b,l,c) * dec_w[o,c] + dec_b[o] : 0
// ============================================================================
__global__ __launch_bounds__(128) void decode_kernel(const int* __restrict__ mask,
                                                     const float* __restrict__ dec_w,
                                                     const float* __restrict__ dec_b,
                                                     float* __restrict__ y) {
    __shared__ float sw[OUTN * CH];
    const int tid = threadIdx.x;
    for (int i = tid; i < OUTN * CH; i += 128) sw[i] = dec_w[i];
    __syncthreads();

    const int b = blockIdx.y;
    const int l = blockIdx.x * 128 + tid;
    const int base = (b * LEN + l) * CH;

    float acc[OUTN];
#pragma unroll
    for (int o = 0; o < OUTN; o++) acc[o] = 0.f;

    for (int c = 0; c < CH; c += 8) {
        uint4 H = *(const uint4*)(g_a_hi + base + c);
        uint4 L = *(const uint4*)(g_a_lo + base + c);
        const __nv_bfloat16* hp = (const __nv_bfloat16*)&H;
        const __nv_bfloat16* lp = (const __nv_bfloat16*)&L;
#pragma unroll
        for (int q = 0; q < 8; q++) {
            float hv = __bfloat162float(hp[q]) + __bfloat162float(lp[q]);
#pragma unroll
            for (int o = 0; o < OUTN; o++) acc[o] = fmaf(hv, sw[o * CH + c + q], acc[o]);
        }
    }

    const int mk = mask[b * LEN + l];
    float* yo = y + (b * LEN + l) * OUTN;
#pragma unroll
    for (int o = 0; o < OUTN; o++) yo[o] = mk ? (acc[o] + dec_b[o]) : 0.f;
}

// ============================================================================
// launch
// ============================================================================
extern "C" void kernel_launch(void* const* d_in, const int* in_sizes, int n_in,
                              void* d_out, int out_size) {
    const int*   x     = (const int*)d_in[0];
    const int*   mask  = (const int*)d_in[1];
    const float* emb   = (const float*)d_in[2];
    const float* w1    = (const float*)d_in[3];
    const float* b1    = (const float*)d_in[4];
    const float* w2    = (const float*)d_in[5];
    const float* b2    = (const float*)d_in[6];
    const float* dec_w = (const float*)d_in[7];
    const float* dec_b = (const float*)d_in[8];
    float*       y     = (float*)d_out;

    cudaFuncSetAttribute(conv_hmma_kernel, cudaFuncAttributeMaxDynamicSharedMemorySize, SMEM_SZ);

    // 1) repack weights (split bf16, k-major)
    {
        const int total = NLEV * 2 * CH * KTOT;
        repack_kernel<<<(total + 255) / 256, 256>>>(w1, w2);
    }
    // 2) embedding gather -> act buffer A
    {
        const int total = BATCH * LEN * CH;
        embed_kernel<<<total / 256, 256>>>(x, emb);
    }
    // 3) TCN levels on tensor cores (HMMA)
    dim3 grid(LEN / TM, CH / TN, BATCH);
    for (int lev = 0; lev < NLEV; lev++) {
        const int d = 1 << lev;
        const int wb1 = (lev * 2 + 0) * CH * KTOT;
        const int wb2 = (lev * 2 + 1) * CH * KTOT;
        conv_hmma_kernel<<<grid, 256, SMEM_SZ>>>(wb1, b1 + lev * CH, d, 0);  // A -> B
        conv_hmma_kernel<<<grid, 256, SMEM_SZ>>>(wb2, b2 + lev * CH, d, 1);  // B (+res A) -> A
    }
    // 4) decode + mask
    decode_kernel<<<dim3(LEN / 128, BATCH), 128>>>(mask, dec_w, dec_b, y);
}